// round 12
// baseline (speedup 1.0000x reference)
#include <cuda_runtime.h>
#include <cuda_bf16.h>
#include <cuda_fp16.h>
#include <cstdint>
#include <cstddef>

#define XD   512
#define HID_ 1024
#define BB   64
#define TT   512
#define G4   4096
#define MROWS 32768
#define NCTA 128
#define THR  256

typedef unsigned long long u64;
typedef unsigned int u32;

// ---------------- device scratch ----------------
__device__ float g_Wh4[(size_t)HID_ * G4];
__device__ float g_b4[G4];
__device__ float g_xproj[(size_t)MROWS * G4];                       // X@Wx + bias
// h in mma A-fragment layout, 4 images: [img(4)][ktile(64)][mtile(4)][lane(32)]
__device__ __align__(16) uint4 g_hfrag[4][64][4][32];
__device__ __align__(16) __nv_bfloat16 g_XH[(size_t)MROWS * XD];
__device__ __align__(16) __nv_bfloat16 g_XL[(size_t)MROWS * XD];
__device__ __align__(16) __nv_bfloat16 g_WXH[(size_t)G4 * XD];
__device__ __align__(16) __nv_bfloat16 g_WXL[(size_t)G4 * XD];
__device__ unsigned g_ckflag[8];          // per-chunk production counters
__device__ unsigned g_done[4];            // per-image consumption counters
__device__ unsigned g_bar_cnt;            // end-of-kernel barrier (replay-safe)
__device__ volatile unsigned g_bar_phase;

// ---------------- helpers ----------------
#define SW128(x) ((x) ^ (((x) >> 3) & 0x70))

__device__ __forceinline__ u32 smem_u32(const void* p) {
    u32 a; asm("{ .reg .u64 t; cvta.to.shared.u64 t, %1; cvt.u32.u64 %0, t; }" : "=r"(a) : "l"(p));
    return a;
}
__device__ __forceinline__ void ldsm4(u32& r0, u32& r1, u32& r2, u32& r3, u32 addr) {
    asm volatile("ldmatrix.sync.aligned.m8n8.x4.shared.b16 {%0,%1,%2,%3}, [%4];"
                 : "=r"(r0), "=r"(r1), "=r"(r2), "=r"(r3) : "r"(addr));
}
__device__ __forceinline__ void mma16816bf(float* c, u32 a0, u32 a1, u32 a2, u32 a3, u32 b0, u32 b1) {
    asm volatile("mma.sync.aligned.m16n8k16.row.col.f32.bf16.bf16.f32 "
                 "{%0,%1,%2,%3}, {%4,%5,%6,%7}, {%8,%9}, {%0,%1,%2,%3};"
                 : "+f"(c[0]), "+f"(c[1]), "+f"(c[2]), "+f"(c[3])
                 : "r"(a0), "r"(a1), "r"(a2), "r"(a3), "r"(b0), "r"(b1));
}
__device__ __forceinline__ void mma16816h(float* c, u32 a0, u32 a1, u32 a2, u32 a3, u32 b0, u32 b1) {
    asm volatile("mma.sync.aligned.m16n8k16.row.col.f32.f16.f16.f32 "
                 "{%0,%1,%2,%3}, {%4,%5,%6,%7}, {%8,%9}, {%0,%1,%2,%3};"
                 : "+f"(c[0]), "+f"(c[1]), "+f"(c[2]), "+f"(c[3])
                 : "r"(a0), "r"(a1), "r"(a2), "r"(a3), "r"(b0), "r"(b1));
}
__device__ __forceinline__ uint4 ldg_cg4(const uint4* p) {
    uint4 v;
    asm volatile("ld.global.cg.v4.u32 {%0,%1,%2,%3}, [%4];"
                 : "=r"(v.x), "=r"(v.y), "=r"(v.z), "=r"(v.w) : "l"(p));
    return v;
}
__device__ __forceinline__ u32 ldg_acq(const unsigned* p) {
    u32 v;
    asm volatile("ld.acquire.gpu.global.u32 %0, [%1];" : "=r"(v) : "l"(p) : "memory");
    return v;
}
__device__ __forceinline__ void cp_async16(u32 dst, const void* src) {
    asm volatile("cp.async.cg.shared.global [%0], [%1], 16;" :: "r"(dst), "l"(src) : "memory");
}
__device__ __forceinline__ void cp_commit() { asm volatile("cp.async.commit_group;" ::: "memory"); }
template<int N> __device__ __forceinline__ void cp_wait() {
    asm volatile("cp.async.wait_group %0;" :: "n"(N) : "memory");
}
__device__ __forceinline__ float sigmoidf_(float x) { return 1.f / (1.f + __expf(-x)); }

__device__ __forceinline__ void bsplit(float v, __nv_bfloat16& hi, __nv_bfloat16& lo) {
    hi = __float2bfloat16(v);
    lo = __float2bfloat16(v - __bfloat162float(hi));
}

// ---------------- kernel 0: pack Wh gate-major + build bf16 images ----------------
__global__ void pack_kernel(const float* __restrict__ X,
                            const float* __restrict__ Wxi, const float* __restrict__ Wxf,
                            const float* __restrict__ Wxo, const float* __restrict__ Wxz,
                            const float* __restrict__ Whi, const float* __restrict__ Whf,
                            const float* __restrict__ Who, const float* __restrict__ Whz,
                            const float* __restrict__ bi,  const float* __restrict__ bf,
                            const float* __restrict__ bo,  const float* __restrict__ bz) {
    int tid0 = blockIdx.x * blockDim.x + threadIdx.x;
    int stride = gridDim.x * blockDim.x;
    for (int idx = tid0; idx < HID_ * G4; idx += stride) {
        int k = idx >> 12, col = idx & 4095, g = col >> 10, j = col & 1023;
        const float* W = (g == 0) ? Whi : (g == 1) ? Whf : (g == 2) ? Who : Whz;
        g_Wh4[idx] = W[k * HID_ + j];
    }
    for (int idx = tid0; idx < G4; idx += stride) {
        int g = idx >> 10, j = idx & 1023;
        const float* b = (g == 0) ? bi : (g == 1) ? bf : (g == 2) ? bo : bz;
        g_b4[idx] = b[j];
    }
    for (int idx = tid0; idx < MROWS * (XD / 4); idx += stride) {
        int m = idx >> 7, kq = (idx & 127) * 4;
        float4 v = *(const float4*)&X[(size_t)m * XD + kq];
        __nv_bfloat16 h[4], l[4];
        bsplit(v.x, h[0], l[0]); bsplit(v.y, h[1], l[1]);
        bsplit(v.z, h[2], l[2]); bsplit(v.w, h[3], l[3]);
        int mt = m >> 7, mloc = m & 127, ck = kq >> 6, kloc = kq & 63;
        size_t off = (size_t)(mt * 8 + ck) * 16384 + (size_t)((mloc >> 3) << 10)
                   + (size_t)SW128(((mloc & 7) << 7) + (kloc << 1));
        *(uint2*)((char*)g_XH + off) = *(uint2*)h;
        *(uint2*)((char*)g_XL + off) = *(uint2*)l;
    }
    for (int idx = tid0; idx < G4 * (XD / 4); idx += stride) {
        int n = idx >> 7, kq = (idx & 127) * 4;
        int g = n >> 10, j = n & 1023;
        const float* W = (g == 0) ? Wxi : (g == 1) ? Wxf : (g == 2) ? Wxo : Wxz;
        __nv_bfloat16 h[4], l[4];
#pragma unroll
        for (int i = 0; i < 4; i++) bsplit(W[(size_t)(kq + i) * HID_ + j], h[i], l[i]);
        int nt = n >> 7, nloc = n & 127, ck = kq >> 6, kloc = kq & 63;
        size_t off = (size_t)(nt * 8 + ck) * 16384 + (size_t)((nloc >> 3) << 10)
                   + (size_t)SW128(((nloc & 7) << 7) + (kloc << 1));
        *(uint2*)((char*)g_WXH + off) = *(uint2*)h;
        *(uint2*)((char*)g_WXL + off) = *(uint2*)l;
    }
}

// ---------------- kernel A: xproj (HMMA bf16 3-product, cp.async pipeline) ----------------
#define XP_SMEM 131072

__global__ __launch_bounds__(512) void xproj_kernel() {
    extern __shared__ __align__(1024) char xs[];
    u32 smem_base = smem_u32(xs);
    int tid = threadIdx.x;
    int lane = tid & 31, wid = tid >> 5;
    int mw = wid & 3, nw = (wid >> 2) & 3;
    int ntb = blockIdx.x, mtb = blockIdx.y;

    int r128 = tid >> 7, lane128 = tid & 127;

    auto issue = [&](int ck, int stage) {
        size_t xb = (size_t)(mtb * 8 + ck) * 16384 + (size_t)lane128 * 16;
        size_t wb = (size_t)(ntb * 8 + ck) * 16384 + (size_t)lane128 * 16;
        const char* src = (r128 == 0) ? (const char*)g_XH + xb
                        : (r128 == 1) ? (const char*)g_XL + xb
                        : (r128 == 2) ? (const char*)g_WXH + wb
                                      : (const char*)g_WXL + wb;
        u32 dst = smem_base + stage * 65536 + r128 * 16384 + lane128 * 16;
#pragma unroll
        for (int q = 0; q < 8; q++) cp_async16(dst + q * 2048, src + q * 2048);
        cp_commit();
    };

    float acc[2][4][4];
#pragma unroll
    for (int i = 0; i < 2; i++)
#pragma unroll
        for (int j = 0; j < 4; j++)
#pragma unroll
            for (int q = 0; q < 4; q++) acc[i][j][q] = 0.f;

    issue(0, 0);

    int kbA = (lane & 16) ? 8 : 0;
    int kbB = lane & 8;
    int ar0 = mw * 32 + (lane & 15);
    int br0 = nw * 32 + (lane & 7) + ((lane & 16) ? 8 : 0);

    for (int ck = 0; ck < 8; ck++) {
        if (ck < 7) { issue(ck + 1, (ck + 1) & 1); cp_wait<1>(); }
        else cp_wait<0>();
        __syncthreads();
        u32 sb = smem_base + (ck & 1) * 65536;
#pragma unroll
        for (int ks = 0; ks < 4; ks++) {
            int klA = ks * 16 + kbA;
            int klB = ks * 16 + kbB;
            u32 ah[2][4], al[2][4], bh[2][4], bl[2][4];
#pragma unroll
            for (int mt2 = 0; mt2 < 2; mt2++) {
                int ar = ar0 + mt2 * 16;
                u32 aoff = (u32)((ar >> 3) << 10) + (u32)SW128(((ar & 7) << 7) + (klA << 1));
                ldsm4(ah[mt2][0], ah[mt2][1], ah[mt2][2], ah[mt2][3], sb + aoff);
                ldsm4(al[mt2][0], al[mt2][1], al[mt2][2], al[mt2][3], sb + 16384 + aoff);
            }
#pragma unroll
            for (int bg = 0; bg < 2; bg++) {
                int br = br0 + bg * 16;
                u32 boff = (u32)((br >> 3) << 10) + (u32)SW128(((br & 7) << 7) + (klB << 1));
                ldsm4(bh[bg][0], bh[bg][1], bh[bg][2], bh[bg][3], sb + 32768 + boff);
                ldsm4(bl[bg][0], bl[bg][1], bl[bg][2], bl[bg][3], sb + 49152 + boff);
            }
#pragma unroll
            for (int mt2 = 0; mt2 < 2; mt2++)
#pragma unroll
                for (int bg = 0; bg < 2; bg++) {
                    float* c0 = acc[mt2][bg * 2];
                    float* c1 = acc[mt2][bg * 2 + 1];
                    mma16816bf(c0, ah[mt2][0], ah[mt2][1], ah[mt2][2], ah[mt2][3], bh[bg][0], bh[bg][1]);
                    mma16816bf(c0, ah[mt2][0], ah[mt2][1], ah[mt2][2], ah[mt2][3], bl[bg][0], bl[bg][1]);
                    mma16816bf(c0, al[mt2][0], al[mt2][1], al[mt2][2], al[mt2][3], bh[bg][0], bh[bg][1]);
                    mma16816bf(c1, ah[mt2][0], ah[mt2][1], ah[mt2][2], ah[mt2][3], bh[bg][2], bh[bg][3]);
                    mma16816bf(c1, ah[mt2][0], ah[mt2][1], ah[mt2][2], ah[mt2][3], bl[bg][2], bl[bg][3]);
                    mma16816bf(c1, al[mt2][0], al[mt2][1], al[mt2][2], al[mt2][3], bh[bg][2], bh[bg][3]);
                }
        }
        __syncthreads();
    }

    int rowb = mtb * 128 + mw * 32;
    int colb = ntb * 128 + nw * 32;
    float2 bias[4];
#pragma unroll
    for (int nc = 0; nc < 4; nc++) {
        int col = colb + (nc >> 1) * 16 + (nc & 1) * 8 + (lane & 3) * 2;
        bias[nc] = *(const float2*)&g_b4[col];
    }
#pragma unroll
    for (int mt2 = 0; mt2 < 2; mt2++) {
        int r0 = rowb + mt2 * 16 + (lane >> 2);
#pragma unroll
        for (int nc = 0; nc < 4; nc++) {
            int col = colb + (nc >> 1) * 16 + (nc & 1) * 8 + (lane & 3) * 2;
            *(float2*)&g_xproj[(size_t)r0 * G4 + col] =
                make_float2(acc[mt2][nc][0] + bias[nc].x, acc[mt2][nc][1] + bias[nc].y);
            *(float2*)&g_xproj[(size_t)(r0 + 8) * G4 + col] =
                make_float2(acc[mt2][nc][2] + bias[nc].x, acc[mt2][nc][3] + bias[nc].y);
        }
    }
}

// ---------------- kernel B: persistent HMMA recurrence, barrier-free chunk flags ----------------
// SMEM: [0,64K) Wh (fp16) | [64K, +34.8K) gsum
#define WHI_OFF   0
#define GSUM_OFF  65536
#define GROW      34
#define SMEM_BYTES (GSUM_OFF + 4 * BB * GROW * 4)
#define IMG_U32   (64 * 4 * 32 * 4)       // one h image in u32 units

__device__ __forceinline__ void grid_sync_final(unsigned& phase) {
    __syncthreads();
    if (threadIdx.x == 0) {
        __threadfence();
        unsigned arrived = atomicAdd(&g_bar_cnt, 1u) + 1u;
        if (arrived == gridDim.x) {
            g_bar_cnt = 0;
            __threadfence();
            g_bar_phase = phase + 1u;
        } else {
            while (g_bar_phase == phase) { }
        }
        phase = phase + 1u;
        __threadfence();
    }
    __syncthreads();
}

__global__ __launch_bounds__(THR, 1) void lstm_kernel(float* __restrict__ out) {
    extern __shared__ __align__(1024) char sm[];
    u32 smem_base = smem_u32(sm);
    float* gsum = (float*)(sm + GSUM_OFF);
    int tid = threadIdx.x;
    int lane = tid & 31, wid = tid >> 5;
    int mt = wid & 1;                 // M-half
    int kq = wid >> 1;                // K-quarter
    int j0 = blockIdx.x * 8;
    int myck = blockIdx.x >> 4;       // chunk this CTA produces
    int cbase = myck;                 // rotated consume order start

    // Wh slice -> single fp16 into SMEM atoms (8rows x 64cols, SW128)
    for (int idx = tid; idx < 32 * 1024; idx += THR) {
        int n = idx & 31, k = idx >> 5;
        int gc = (n >> 3) * 1024 + j0 + (n & 7);
        float wv = g_Wh4[(size_t)k * G4 + gc];
        __half hi = __float2half_rn(wv);
        u32 off = (u32)((n >> 3) + ((k >> 6) << 2)) * 1024u
                + (u32)SW128(((n & 7) << 7) + ((k & 63) << 1));
        *(__half*)(sm + WHI_OFF + off) = hi;
    }

    // ---- activation thread ownership + fragment write slot ----
    int ab = tid >> 2;                     // batch row 0..63
    int ajp = (tid & 3) * 2;               // j pair within CTA's 8 cols
    int rm = ab & 15;
    int w_mtile = ab >> 4;
    int w_ktile = blockIdx.x >> 1;
    int w_L = (rm & 7) * 4 + (tid & 3);
    int w_r = ((rm >> 3) & 1) + ((blockIdx.x & 1) << 1);
    u32* wp = (u32*)&g_hfrag[0][w_ktile][w_mtile][w_L] + w_r;
    *wp = 0u;                              // zero image 0 (h[0])
    float c0s = 0.f, c1s = 0.f;

    // publish h[0]: production round 1 for my chunk
    __syncthreads();
    if (tid == 0) { __threadfence(); atomicAdd(&g_ckflag[myck], 1u); }

    // mma B fragment address components
    int bcol_b = (lane & 7) + ((lane & 16) ? 8 : 0);
    int kbitB = lane & 8;

    unsigned phase = 0;
    if (tid == 0) phase = g_bar_phase;

    const size_t xbase = ((size_t)ab * TT) * G4 + j0 + ajp;

    for (int t = 0; t < TT; t++) {
        const uint4* fH = &g_hfrag[t & 3][0][0][0];
        u32 tgt = 16u * (u32)(t + 1);

        // xproj loads for this step (resolve under chunk waits / mma)
        float2 xpv[4];
#pragma unroll
        for (int g = 0; g < 4; g++)
            xpv[g] = *(const float2*)&g_xproj[xbase + (size_t)t * G4 + (size_t)g * 1024];

        float acc[2][4][4];
#pragma unroll
        for (int s = 0; s < 2; s++)
#pragma unroll
            for (int n = 0; n < 4; n++)
#pragma unroll
                for (int q = 0; q < 4; q++) acc[s][n][q] = 0.f;

        // rotating 3-slot A buffer; wait chunk flag then load, 2 ahead
        uint4 A[3][2][2];
#pragma unroll
        for (int pf = 0; pf < 2; pf++) {
            int ck = (cbase + pf) & 7;
            while (ldg_acq(&g_ckflag[ck]) < tgt) { }
#pragma unroll
            for (int ks = 0; ks < 2; ks++)
#pragma unroll
                for (int sub = 0; sub < 2; sub++)
                    A[pf][ks][sub] = ldg_cg4(fH + ((ck * 8 + kq * 2 + ks) * 4 + (mt * 2 + sub)) * 32 + lane);
        }

#pragma unroll
        for (int i = 0; i < 8; i++) {
            int ck = (cbase + i) & 7;
            if (i + 2 < 8) {
                int ck2 = (cbase + i + 2) & 7;
                while (ldg_acq(&g_ckflag[ck2]) < tgt) { }
#pragma unroll
                for (int ks = 0; ks < 2; ks++)
#pragma unroll
                    for (int sub = 0; sub < 2; sub++)
                        A[(i + 2) % 3][ks][sub] =
                            ldg_cg4(fH + ((ck2 * 8 + kq * 2 + ks) * 4 + (mt * 2 + sub)) * 32 + lane);
            }
#pragma unroll
            for (int ks = 0; ks < 2; ks++) {
                int kB = ck * 128 + kq * 32 + ks * 16 + kbitB;
                u32 bh[2][4];
#pragma unroll
                for (int g16 = 0; g16 < 2; g16++) {
                    int bc = bcol_b + g16 * 16;
                    u32 boff = (u32)((bc >> 3) + ((kB >> 6) << 2)) * 1024u
                             + (u32)SW128(((bc & 7) << 7) + ((kB & 63) << 1));
                    ldsm4(bh[g16][0], bh[g16][1], bh[g16][2], bh[g16][3], smem_base + WHI_OFF + boff);
                }
#pragma unroll
                for (int sub = 0; sub < 2; sub++) {
                    uint4 ah = A[i % 3][ks][sub];
#pragma unroll
                    for (int g16 = 0; g16 < 2; g16++) {
                        mma16816h(acc[sub][g16 * 2],     ah.x, ah.y, ah.z, ah.w, bh[g16][0], bh[g16][1]);
                        mma16816h(acc[sub][g16 * 2 + 1], ah.x, ah.y, ah.z, ah.w, bh[g16][2], bh[g16][3]);
                    }
                }
            }
        }

        // fragment writeback: per-warp K-quarter region
        {
            float* gq = gsum + (size_t)kq * BB * GROW;
#pragma unroll
            for (int sub = 0; sub < 2; sub++) {
                int r0 = mt * 32 + sub * 16 + (lane >> 2);
#pragma unroll
                for (int n8 = 0; n8 < 4; n8++) {
                    int cb = n8 * 8 + (lane & 3) * 2;
                    *(float2*)&gq[r0 * GROW + cb]       = make_float2(acc[sub][n8][0], acc[sub][n8][1]);
                    *(float2*)&gq[(r0 + 8) * GROW + cb] = make_float2(acc[sub][n8][2], acc[sub][n8][3]);
                }
            }
        }
        __syncthreads();   // mma complete CTA-wide; gsum visible

        // consumption bookkeeping + lagged anti-overwrite guard for image (t+1)&3
        if (tid == 0) {
            atomicAdd(&g_done[t & 3], 1u);
            if (t >= 3) {
                unsigned thr = 128u * (((unsigned)(t - 3) >> 2) + 1u);
                while (ldg_acq(&g_done[(t + 1) & 3]) < thr) { }
            }
        }
        __syncthreads();

        // activation: 2 cells per thread, sum 4 K-quarters
        {
            float gg[4][2];
#pragma unroll
            for (int g = 0; g < 4; g++) { gg[g][0] = xpv[g].x; gg[g][1] = xpv[g].y; }
#pragma unroll
            for (int q = 0; q < 4; q++) {
                const float* gq = gsum + (size_t)q * BB * GROW + ab * GROW + ajp;
#pragma unroll
                for (int g = 0; g < 4; g++) {
                    float2 v = *(const float2*)&gq[g * 8];
                    gg[g][0] += v.x; gg[g][1] += v.y;
                }
            }
            float i0 = sigmoidf_(gg[0][0]), f0 = sigmoidf_(gg[1][0]), o0 = sigmoidf_(gg[2][0]), z0 = tanhf(gg[3][0]);
            float i1 = sigmoidf_(gg[0][1]), f1 = sigmoidf_(gg[1][1]), o1 = sigmoidf_(gg[2][1]), z1 = tanhf(gg[3][1]);
            c0s = i0 * z0 + f0 * c0s;
            c1s = i1 * z1 + f1 * c1s;
            float hv0 = o0 * tanhf(c0s);
            float hv1 = o1 * tanhf(c1s);
            *(float2*)&out[((size_t)ab * TT + t) * HID_ + j0 + ajp] = make_float2(hv0, hv1);
            __half h0 = __float2half_rn(hv0);
            __half h1 = __float2half_rn(hv1);
            u32 hw = (u32)__half_as_ushort(h0) | ((u32)__half_as_ushort(h1) << 16);
            wp[(size_t)((t + 1) & 3) * IMG_U32] = hw;
        }

        // publish h[t+1] for my chunk
        __syncthreads();
        if (tid == 0) { __threadfence(); atomicAdd(&g_ckflag[myck], 1u); }
    }

    // replay-safe epilogue: full-grid barrier, then reset counters
    grid_sync_final(phase);
    if (blockIdx.x == 0 && tid == 0) {
#pragma unroll
        for (int i = 0; i < 8; i++) g_ckflag[i] = 0u;
#pragma unroll
        for (int i = 0; i < 4; i++) g_done[i] = 0u;
        __threadfence();
    }
}

// ---------------- launch ----------------
extern "C" void kernel_launch(void* const* d_in, const int* in_sizes, int n_in,
                              void* d_out, int out_size) {
    const float* X   = (const float*)d_in[0];
    const float* Whi = (const float*)d_in[1];
    const float* Wxi = (const float*)d_in[2];
    const float* bi  = (const float*)d_in[3];
    const float* Whf = (const float*)d_in[4];
    const float* Wxf = (const float*)d_in[5];
    const float* bf  = (const float*)d_in[6];
    const float* Who = (const float*)d_in[7];
    const float* Wxo = (const float*)d_in[8];
    const float* bo  = (const float*)d_in[9];
    const float* Whz = (const float*)d_in[10];
    const float* Wxz = (const float*)d_in[11];
    const float* bz  = (const float*)d_in[12];

    pack_kernel<<<2048, 256>>>(X, Wxi, Wxf, Wxo, Wxz, Whi, Whf, Who, Whz, bi, bf, bo, bz);

    cudaFuncSetAttribute(xproj_kernel, cudaFuncAttributeMaxDynamicSharedMemorySize, XP_SMEM);
    dim3 gA(32, 256);
    xproj_kernel<<<gA, 512, XP_SMEM>>>();

    cudaFuncSetAttribute(lstm_kernel, cudaFuncAttributeMaxDynamicSharedMemorySize, SMEM_BYTES);
    lstm_kernel<<<NCTA, THR, SMEM_BYTES>>>((float*)d_out);
}

// round 13
// speedup vs baseline: 1.0205x; 1.0205x over previous
#include <cuda_runtime.h>
#include <cuda_bf16.h>
#include <cuda_fp16.h>
#include <cstdint>
#include <cstddef>

#define XD   512
#define HID_ 1024
#define BB   64
#define TT   512
#define G4   4096
#define MROWS 32768
#define NCTA 128
#define THR  256

typedef unsigned long long u64;
typedef unsigned int u32;

// ---------------- device scratch ----------------
__device__ float g_Wh4[(size_t)HID_ * G4];
__device__ float g_b4[G4];
__device__ float g_xproj[(size_t)MROWS * G4];                       // X@Wx + bias
// h in mma A-fragment layout (single fp16 image, dbl-buffered): [parity][ktile(64)][mtile(4)][lane(32)]
__device__ __align__(16) uint4 g_hfrag[2][64][4][32];
__device__ __align__(16) __nv_bfloat16 g_XH[(size_t)MROWS * XD];
__device__ __align__(16) __nv_bfloat16 g_XL[(size_t)MROWS * XD];
__device__ __align__(16) __nv_bfloat16 g_WXH[(size_t)G4 * XD];
__device__ __align__(16) __nv_bfloat16 g_WXL[(size_t)G4 * XD];
__device__ unsigned g_bar_cnt;
__device__ volatile unsigned g_bar_phase;

// ---------------- helpers ----------------
#define SW128(x) ((x) ^ (((x) >> 3) & 0x70))

__device__ __forceinline__ u32 smem_u32(const void* p) {
    u32 a; asm("{ .reg .u64 t; cvta.to.shared.u64 t, %1; cvt.u32.u64 %0, t; }" : "=r"(a) : "l"(p));
    return a;
}
__device__ __forceinline__ void ldsm4(u32& r0, u32& r1, u32& r2, u32& r3, u32 addr) {
    asm volatile("ldmatrix.sync.aligned.m8n8.x4.shared.b16 {%0,%1,%2,%3}, [%4];"
                 : "=r"(r0), "=r"(r1), "=r"(r2), "=r"(r3) : "r"(addr));
}
__device__ __forceinline__ void mma16816bf(float* c, u32 a0, u32 a1, u32 a2, u32 a3, u32 b0, u32 b1) {
    asm volatile("mma.sync.aligned.m16n8k16.row.col.f32.bf16.bf16.f32 "
                 "{%0,%1,%2,%3}, {%4,%5,%6,%7}, {%8,%9}, {%0,%1,%2,%3};"
                 : "+f"(c[0]), "+f"(c[1]), "+f"(c[2]), "+f"(c[3])
                 : "r"(a0), "r"(a1), "r"(a2), "r"(a3), "r"(b0), "r"(b1));
}
__device__ __forceinline__ void mma16816h(float* c, u32 a0, u32 a1, u32 a2, u32 a3, u32 b0, u32 b1) {
    asm volatile("mma.sync.aligned.m16n8k16.row.col.f32.f16.f16.f32 "
                 "{%0,%1,%2,%3}, {%4,%5,%6,%7}, {%8,%9}, {%0,%1,%2,%3};"
                 : "+f"(c[0]), "+f"(c[1]), "+f"(c[2]), "+f"(c[3])
                 : "r"(a0), "r"(a1), "r"(a2), "r"(a3), "r"(b0), "r"(b1));
}
__device__ __forceinline__ uint4 ldg_cg4(const uint4* p) {
    uint4 v;
    asm volatile("ld.global.cg.v4.u32 {%0,%1,%2,%3}, [%4];"
                 : "=r"(v.x), "=r"(v.y), "=r"(v.z), "=r"(v.w) : "l"(p));
    return v;
}
__device__ __forceinline__ void cp_async16(u32 dst, const void* src) {
    asm volatile("cp.async.cg.shared.global [%0], [%1], 16;" :: "r"(dst), "l"(src) : "memory");
}
__device__ __forceinline__ void cp_commit() { asm volatile("cp.async.commit_group;" ::: "memory"); }
template<int N> __device__ __forceinline__ void cp_wait() {
    asm volatile("cp.async.wait_group %0;" :: "n"(N) : "memory");
}
__device__ __forceinline__ float sigmoidf_(float x) {
    return __fdividef(1.f, 1.f + __expf(-x));
}
__device__ __forceinline__ float tanhf_fast(float x) {
    float e = __expf(-2.f * x);
    return __fdividef(1.f - e, 1.f + e);
}

__device__ __forceinline__ void bsplit(float v, __nv_bfloat16& hi, __nv_bfloat16& lo) {
    hi = __float2bfloat16(v);
    lo = __float2bfloat16(v - __bfloat162float(hi));
}

// ---------------- kernel 0: pack Wh gate-major + build bf16 images ----------------
__global__ void pack_kernel(const float* __restrict__ X,
                            const float* __restrict__ Wxi, const float* __restrict__ Wxf,
                            const float* __restrict__ Wxo, const float* __restrict__ Wxz,
                            const float* __restrict__ Whi, const float* __restrict__ Whf,
                            const float* __restrict__ Who, const float* __restrict__ Whz,
                            const float* __restrict__ bi,  const float* __restrict__ bf,
                            const float* __restrict__ bo,  const float* __restrict__ bz) {
    int tid0 = blockIdx.x * blockDim.x + threadIdx.x;
    int stride = gridDim.x * blockDim.x;
    for (int idx = tid0; idx < HID_ * G4; idx += stride) {
        int k = idx >> 12, col = idx & 4095, g = col >> 10, j = col & 1023;
        const float* W = (g == 0) ? Whi : (g == 1) ? Whf : (g == 2) ? Who : Whz;
        g_Wh4[idx] = W[k * HID_ + j];
    }
    for (int idx = tid0; idx < G4; idx += stride) {
        int g = idx >> 10, j = idx & 1023;
        const float* b = (g == 0) ? bi : (g == 1) ? bf : (g == 2) ? bo : bz;
        g_b4[idx] = b[j];
    }
    for (int idx = tid0; idx < MROWS * (XD / 4); idx += stride) {
        int m = idx >> 7, kq = (idx & 127) * 4;
        float4 v = *(const float4*)&X[(size_t)m * XD + kq];
        __nv_bfloat16 h[4], l[4];
        bsplit(v.x, h[0], l[0]); bsplit(v.y, h[1], l[1]);
        bsplit(v.z, h[2], l[2]); bsplit(v.w, h[3], l[3]);
        int mt = m >> 7, mloc = m & 127, ck = kq >> 6, kloc = kq & 63;
        size_t off = (size_t)(mt * 8 + ck) * 16384 + (size_t)((mloc >> 3) << 10)
                   + (size_t)SW128(((mloc & 7) << 7) + (kloc << 1));
        *(uint2*)((char*)g_XH + off) = *(uint2*)h;
        *(uint2*)((char*)g_XL + off) = *(uint2*)l;
    }
    for (int idx = tid0; idx < G4 * (XD / 4); idx += stride) {
        int n = idx >> 7, kq = (idx & 127) * 4;
        int g = n >> 10, j = n & 1023;
        const float* W = (g == 0) ? Wxi : (g == 1) ? Wxf : (g == 2) ? Wxo : Wxz;
        __nv_bfloat16 h[4], l[4];
#pragma unroll
        for (int i = 0; i < 4; i++) bsplit(W[(size_t)(kq + i) * HID_ + j], h[i], l[i]);
        int nt = n >> 7, nloc = n & 127, ck = kq >> 6, kloc = kq & 63;
        size_t off = (size_t)(nt * 8 + ck) * 16384 + (size_t)((nloc >> 3) << 10)
                   + (size_t)SW128(((nloc & 7) << 7) + (kloc << 1));
        *(uint2*)((char*)g_WXH + off) = *(uint2*)h;
        *(uint2*)((char*)g_WXL + off) = *(uint2*)l;
    }
}

// ---------------- kernel A: xproj (HMMA bf16 3-product, cp.async pipeline) ----------------
#define XP_SMEM 131072

__global__ __launch_bounds__(512) void xproj_kernel() {
    extern __shared__ __align__(1024) char xs[];
    u32 smem_base = smem_u32(xs);
    int tid = threadIdx.x;
    int lane = tid & 31, wid = tid >> 5;
    int mw = wid & 3, nw = (wid >> 2) & 3;
    int ntb = blockIdx.x, mtb = blockIdx.y;

    int r128 = tid >> 7, lane128 = tid & 127;

    auto issue = [&](int ck, int stage) {
        size_t xb = (size_t)(mtb * 8 + ck) * 16384 + (size_t)lane128 * 16;
        size_t wb = (size_t)(ntb * 8 + ck) * 16384 + (size_t)lane128 * 16;
        const char* src = (r128 == 0) ? (const char*)g_XH + xb
                        : (r128 == 1) ? (const char*)g_XL + xb
                        : (r128 == 2) ? (const char*)g_WXH + wb
                                      : (const char*)g_WXL + wb;
        u32 dst = smem_base + stage * 65536 + r128 * 16384 + lane128 * 16;
#pragma unroll
        for (int q = 0; q < 8; q++) cp_async16(dst + q * 2048, src + q * 2048);
        cp_commit();
    };

    float acc[2][4][4];
#pragma unroll
    for (int i = 0; i < 2; i++)
#pragma unroll
        for (int j = 0; j < 4; j++)
#pragma unroll
            for (int q = 0; q < 4; q++) acc[i][j][q] = 0.f;

    issue(0, 0);

    int kbA = (lane & 16) ? 8 : 0;
    int kbB = lane & 8;
    int ar0 = mw * 32 + (lane & 15);
    int br0 = nw * 32 + (lane & 7) + ((lane & 16) ? 8 : 0);

    for (int ck = 0; ck < 8; ck++) {
        if (ck < 7) { issue(ck + 1, (ck + 1) & 1); cp_wait<1>(); }
        else cp_wait<0>();
        __syncthreads();
        u32 sb = smem_base + (ck & 1) * 65536;
#pragma unroll
        for (int ks = 0; ks < 4; ks++) {
            int klA = ks * 16 + kbA;
            int klB = ks * 16 + kbB;
            u32 ah[2][4], al[2][4], bh[2][4], bl[2][4];
#pragma unroll
            for (int mt2 = 0; mt2 < 2; mt2++) {
                int ar = ar0 + mt2 * 16;
                u32 aoff = (u32)((ar >> 3) << 10) + (u32)SW128(((ar & 7) << 7) + (klA << 1));
                ldsm4(ah[mt2][0], ah[mt2][1], ah[mt2][2], ah[mt2][3], sb + aoff);
                ldsm4(al[mt2][0], al[mt2][1], al[mt2][2], al[mt2][3], sb + 16384 + aoff);
            }
#pragma unroll
            for (int bg = 0; bg < 2; bg++) {
                int br = br0 + bg * 16;
                u32 boff = (u32)((br >> 3) << 10) + (u32)SW128(((br & 7) << 7) + (klB << 1));
                ldsm4(bh[bg][0], bh[bg][1], bh[bg][2], bh[bg][3], sb + 32768 + boff);
                ldsm4(bl[bg][0], bl[bg][1], bl[bg][2], bl[bg][3], sb + 49152 + boff);
            }
#pragma unroll
            for (int mt2 = 0; mt2 < 2; mt2++)
#pragma unroll
                for (int bg = 0; bg < 2; bg++) {
                    float* c0 = acc[mt2][bg * 2];
                    float* c1 = acc[mt2][bg * 2 + 1];
                    mma16816bf(c0, ah[mt2][0], ah[mt2][1], ah[mt2][2], ah[mt2][3], bh[bg][0], bh[bg][1]);
                    mma16816bf(c0, ah[mt2][0], ah[mt2][1], ah[mt2][2], ah[mt2][3], bl[bg][0], bl[bg][1]);
                    mma16816bf(c0, al[mt2][0], al[mt2][1], al[mt2][2], al[mt2][3], bh[bg][0], bh[bg][1]);
                    mma16816bf(c1, ah[mt2][0], ah[mt2][1], ah[mt2][2], ah[mt2][3], bh[bg][2], bh[bg][3]);
                    mma16816bf(c1, ah[mt2][0], ah[mt2][1], ah[mt2][2], ah[mt2][3], bl[bg][2], bl[bg][3]);
                    mma16816bf(c1, al[mt2][0], al[mt2][1], al[mt2][2], al[mt2][3], bh[bg][2], bh[bg][3]);
                }
        }
        __syncthreads();
    }

    int rowb = mtb * 128 + mw * 32;
    int colb = ntb * 128 + nw * 32;
    float2 bias[4];
#pragma unroll
    for (int nc = 0; nc < 4; nc++) {
        int col = colb + (nc >> 1) * 16 + (nc & 1) * 8 + (lane & 3) * 2;
        bias[nc] = *(const float2*)&g_b4[col];
    }
#pragma unroll
    for (int mt2 = 0; mt2 < 2; mt2++) {
        int r0 = rowb + mt2 * 16 + (lane >> 2);
#pragma unroll
        for (int nc = 0; nc < 4; nc++) {
            int col = colb + (nc >> 1) * 16 + (nc & 1) * 8 + (lane & 3) * 2;
            *(float2*)&g_xproj[(size_t)r0 * G4 + col] =
                make_float2(acc[mt2][nc][0] + bias[nc].x, acc[mt2][nc][1] + bias[nc].y);
            *(float2*)&g_xproj[(size_t)(r0 + 8) * G4 + col] =
                make_float2(acc[mt2][nc][2] + bias[nc].x, acc[mt2][nc][3] + bias[nc].y);
        }
    }
}

// ---------------- kernel B: persistent HMMA recurrence (B-in-registers, chunk-per-warp) ----------------
// SMEM: [0,64K) Wh (fp16, prologue only) | [64K, +69.6K) gsum (8 regions)
#define WHI_OFF   0
#define GSUM_OFF  65536
#define GROW      34
#define SMEM_BYTES (GSUM_OFF + 8 * BB * GROW * 4)
#define IMG_U32   (64 * 4 * 32 * 4)

__device__ __forceinline__ void grid_sync(unsigned& phase) {
    __syncthreads();
    if (threadIdx.x == 0) {
        __threadfence();
        unsigned arrived = atomicAdd(&g_bar_cnt, 1u) + 1u;
        if (arrived == gridDim.x) {
            g_bar_cnt = 0;
            __threadfence();
            g_bar_phase = phase + 1u;
        } else {
            while (g_bar_phase == phase) { }
        }
        phase = phase + 1u;
        __threadfence();
    }
    __syncthreads();
}

__global__ __launch_bounds__(THR, 1) void lstm_kernel(float* __restrict__ out) {
    extern __shared__ __align__(1024) char sm[];
    u32 smem_base = smem_u32(sm);
    float* gsum = (float*)(sm + GSUM_OFF);
    int tid = threadIdx.x;
    int lane = tid & 31, wid = tid >> 5;    // warp owns K-chunk 'wid' (128 k), full M=64
    int j0 = blockIdx.x * 8;

    // Wh slice -> single fp16 into SMEM atoms (8rows x 64cols, SW128); prologue only
    for (int idx = tid; idx < 32 * 1024; idx += THR) {
        int n = idx & 31, k = idx >> 5;
        int gc = (n >> 3) * 1024 + j0 + (n & 7);
        float wv = g_Wh4[(size_t)k * G4 + gc];
        __half hi = __float2half_rn(wv);
        u32 off = (u32)((n >> 3) + ((k >> 6) << 2)) * 1024u
                + (u32)SW128(((n & 7) << 7) + ((k & 63) << 1));
        *(__half*)(sm + WHI_OFF + off) = hi;
    }
    __syncthreads();

    // preload B fragments for this warp's chunk into registers (once)
    int bcol_b = (lane & 7) + ((lane & 16) ? 8 : 0);
    int kbitB = lane & 8;
    u32 B[8][2][4];
#pragma unroll
    for (int k16 = 0; k16 < 8; k16++) {
        int kB = wid * 128 + k16 * 16 + kbitB;
#pragma unroll
        for (int g16 = 0; g16 < 2; g16++) {
            int bc = bcol_b + g16 * 16;
            u32 boff = (u32)((bc >> 3) + ((kB >> 6) << 2)) * 1024u
                     + (u32)SW128(((bc & 7) << 7) + ((kB & 63) << 1));
            ldsm4(B[k16][g16][0], B[k16][g16][1], B[k16][g16][2], B[k16][g16][3],
                  smem_base + WHI_OFF + boff);
        }
    }

    // ---- activation thread ownership + fragment write slot ----
    int ab = tid >> 2;                     // batch row 0..63
    int ajp = (tid & 3) * 2;               // j pair within CTA's 8 cols
    int rm = ab & 15;
    int w_mtile = ab >> 4;
    int w_ktile = blockIdx.x >> 1;
    int w_L = (rm & 7) * 4 + (tid & 3);
    int w_r = ((rm >> 3) & 1) + ((blockIdx.x & 1) << 1);
    u32* wp = (u32*)&g_hfrag[0][w_ktile][w_mtile][w_L] + w_r;
    const size_t PAR_STRIDE_U32 = 64ull * 4 * 32 * 4;
    *wp = 0u;                              // zero parity-0 image
    float c0s = 0.f, c1s = 0.f;

    unsigned phase = 0;
    if (tid == 0) phase = g_bar_phase;

    // xproj prefetch for step 0
    const size_t xbase = ((size_t)ab * TT) * G4 + j0 + ajp;
    float2 xpv[4], xpn[4];
#pragma unroll
    for (int g = 0; g < 4; g++)
        xpv[g] = *(const float2*)&g_xproj[xbase + (size_t)g * 1024];

    grid_sync(phase);

    const int fbase = wid * 8;             // my chunk's first ktile

    for (int t = 0; t < TT; t++) {
        int par = t & 1, npn = par ^ 1;
        const uint4* fH = &g_hfrag[par][0][0][0];

        float acc[4][4][4];
#pragma unroll
        for (int m = 0; m < 4; m++)
#pragma unroll
            for (int n = 0; n < 4; n++)
#pragma unroll
                for (int q = 0; q < 4; q++) acc[m][n][q] = 0.f;

        // rotating 3-slot A buffer (per k16: 4 mtiles)
        uint4 A[3][4];
#pragma unroll
        for (int pf = 0; pf < 2; pf++)
#pragma unroll
            for (int m = 0; m < 4; m++)
                A[pf][m] = ldg_cg4(fH + ((fbase + pf) * 4 + m) * 32 + lane);

#pragma unroll
        for (int k16 = 0; k16 < 8; k16++) {
            if (k16 + 2 < 8) {
#pragma unroll
                for (int m = 0; m < 4; m++)
                    A[(k16 + 2) % 3][m] = ldg_cg4(fH + ((fbase + k16 + 2) * 4 + m) * 32 + lane);
            }
#pragma unroll
            for (int m = 0; m < 4; m++) {
                uint4 ah = A[k16 % 3][m];
#pragma unroll
                for (int g16 = 0; g16 < 2; g16++) {
                    mma16816h(acc[m][g16 * 2],     ah.x, ah.y, ah.z, ah.w, B[k16][g16][0], B[k16][g16][1]);
                    mma16816h(acc[m][g16 * 2 + 1], ah.x, ah.y, ah.z, ah.w, B[k16][g16][2], B[k16][g16][3]);
                }
            }
        }

        // fragment writeback: per-warp region (8 regions)
        {
            float* gq = gsum + (size_t)wid * BB * GROW;
#pragma unroll
            for (int m = 0; m < 4; m++) {
                int r0 = m * 16 + (lane >> 2);
#pragma unroll
                for (int n8 = 0; n8 < 4; n8++) {
                    int cb = n8 * 8 + (lane & 3) * 2;
                    *(float2*)&gq[r0 * GROW + cb]       = make_float2(acc[m][n8][0], acc[m][n8][1]);
                    *(float2*)&gq[(r0 + 8) * GROW + cb] = make_float2(acc[m][n8][2], acc[m][n8][3]);
                }
            }
        }
        __syncthreads();

        // activation: 2 cells per thread, sum 8 chunk-regions
        {
            float gg[4][2];
#pragma unroll
            for (int g = 0; g < 4; g++) { gg[g][0] = xpv[g].x; gg[g][1] = xpv[g].y; }
#pragma unroll
            for (int q = 0; q < 8; q++) {
                const float* gq = gsum + (size_t)q * BB * GROW + ab * GROW + ajp;
#pragma unroll
                for (int g = 0; g < 4; g++) {
                    float2 v = *(const float2*)&gq[g * 8];
                    gg[g][0] += v.x; gg[g][1] += v.y;
                }
            }
            float i0 = sigmoidf_(gg[0][0]), f0 = sigmoidf_(gg[1][0]), o0 = sigmoidf_(gg[2][0]), z0 = tanhf_fast(gg[3][0]);
            float i1 = sigmoidf_(gg[0][1]), f1 = sigmoidf_(gg[1][1]), o1 = sigmoidf_(gg[2][1]), z1 = tanhf_fast(gg[3][1]);
            c0s = i0 * z0 + f0 * c0s;
            c1s = i1 * z1 + f1 * c1s;
            float hv0 = o0 * tanhf_fast(c0s);
            float hv1 = o1 * tanhf_fast(c1s);
            // h-frag store FIRST (critical path), out store after (fire-and-forget)
            __half h0 = __float2half_rn(hv0);
            __half h1 = __float2half_rn(hv1);
            u32 hw = (u32)__half_as_ushort(h0) | ((u32)__half_as_ushort(h1) << 16);
            wp[(size_t)npn * PAR_STRIDE_U32] = hw;
            *(float2*)&out[((size_t)ab * TT + t) * HID_ + j0 + ajp] = make_float2(hv0, hv1);
        }

        // prefetch next-step xproj BEFORE the barrier (resolves during the wait)
        if (t + 1 < TT) {
#pragma unroll
            for (int g = 0; g < 4; g++)
                xpn[g] = *(const float2*)&g_xproj[xbase + (size_t)(t + 1) * G4 + (size_t)g * 1024];
            grid_sync(phase);
#pragma unroll
            for (int g = 0; g < 4; g++) xpv[g] = xpn[g];
        }
    }
}

// ---------------- launch ----------------
extern "C" void kernel_launch(void* const* d_in, const int* in_sizes, int n_in,
                              void* d_out, int out_size) {
    const float* X   = (const float*)d_in[0];
    const float* Whi = (const float*)d_in[1];
    const float* Wxi = (const float*)d_in[2];
    const float* bi  = (const float*)d_in[3];
    const float* Whf = (const float*)d_in[4];
    const float* Wxf = (const float*)d_in[5];
    const float* bf  = (const float*)d_in[6];
    const float* Who = (const float*)d_in[7];
    const float* Wxo = (const float*)d_in[8];
    const float* bo  = (const float*)d_in[9];
    const float* Whz = (const float*)d_in[10];
    const float* Wxz = (const float*)d_in[11];
    const float* bz  = (const float*)d_in[12];

    pack_kernel<<<2048, 256>>>(X, Wxi, Wxf, Wxo, Wxz, Whi, Whf, Who, Whz, bi, bf, bo, bz);

    cudaFuncSetAttribute(xproj_kernel, cudaFuncAttributeMaxDynamicSharedMemorySize, XP_SMEM);
    dim3 gA(32, 256);
    xproj_kernel<<<gA, 512, XP_SMEM>>>();

    cudaFuncSetAttribute(lstm_kernel, cudaFuncAttributeMaxDynamicSharedMemorySize, SMEM_BYTES);
    lstm_kernel<<<NCTA, THR, SMEM_BYTES>>>((float*)d_out);
}

// round 14
// speedup vs baseline: 1.0993x; 1.0773x over previous
#include <cuda_runtime.h>
#include <cuda_bf16.h>
#include <cuda_fp16.h>
#include <cstdint>
#include <cstddef>

#define XD   512
#define HID_ 1024
#define BB   64
#define TT   512
#define G4   4096
#define MROWS 32768
#define NCTA 128
#define THR  256

typedef unsigned long long u64;
typedef unsigned int u32;

// ---------------- device scratch ----------------
__device__ float g_Wh4[(size_t)HID_ * G4];
__device__ float g_b4[G4];
__device__ float g_xproj[(size_t)MROWS * G4];                       // X@Wx + bias
// h stored directly in mma A-fragment layout (single fp16 image): [parity][ktile(64)][mtile(4)][lane(32)]
__device__ __align__(16) uint4 g_hfrag[2][64][4][32];
__device__ __align__(16) __nv_bfloat16 g_XH[(size_t)MROWS * XD];
__device__ __align__(16) __nv_bfloat16 g_XL[(size_t)MROWS * XD];
__device__ __align__(16) __nv_bfloat16 g_WXH[(size_t)G4 * XD];
__device__ __align__(16) __nv_bfloat16 g_WXL[(size_t)G4 * XD];
__device__ unsigned g_bar_cnt;
__device__ volatile unsigned g_bar_phase;

// ---------------- helpers ----------------
#define SW128(x) ((x) ^ (((x) >> 3) & 0x70))

__device__ __forceinline__ u32 smem_u32(const void* p) {
    u32 a; asm("{ .reg .u64 t; cvta.to.shared.u64 t, %1; cvt.u32.u64 %0, t; }" : "=r"(a) : "l"(p));
    return a;
}
__device__ __forceinline__ void ldsm4(u32& r0, u32& r1, u32& r2, u32& r3, u32 addr) {
    asm volatile("ldmatrix.sync.aligned.m8n8.x4.shared.b16 {%0,%1,%2,%3}, [%4];"
                 : "=r"(r0), "=r"(r1), "=r"(r2), "=r"(r3) : "r"(addr));
}
__device__ __forceinline__ void mma16816bf(float* c, u32 a0, u32 a1, u32 a2, u32 a3, u32 b0, u32 b1) {
    asm volatile("mma.sync.aligned.m16n8k16.row.col.f32.bf16.bf16.f32 "
                 "{%0,%1,%2,%3}, {%4,%5,%6,%7}, {%8,%9}, {%0,%1,%2,%3};"
                 : "+f"(c[0]), "+f"(c[1]), "+f"(c[2]), "+f"(c[3])
                 : "r"(a0), "r"(a1), "r"(a2), "r"(a3), "r"(b0), "r"(b1));
}
__device__ __forceinline__ void mma16816h(float* c, u32 a0, u32 a1, u32 a2, u32 a3, u32 b0, u32 b1) {
    asm volatile("mma.sync.aligned.m16n8k16.row.col.f32.f16.f16.f32 "
                 "{%0,%1,%2,%3}, {%4,%5,%6,%7}, {%8,%9}, {%0,%1,%2,%3};"
                 : "+f"(c[0]), "+f"(c[1]), "+f"(c[2]), "+f"(c[3])
                 : "r"(a0), "r"(a1), "r"(a2), "r"(a3), "r"(b0), "r"(b1));
}
__device__ __forceinline__ uint4 ldg_cg4(const uint4* p) {
    uint4 v;
    asm volatile("ld.global.cg.v4.u32 {%0,%1,%2,%3}, [%4];"
                 : "=r"(v.x), "=r"(v.y), "=r"(v.z), "=r"(v.w) : "l"(p));
    return v;
}
__device__ __forceinline__ void cp_async16(u32 dst, const void* src) {
    asm volatile("cp.async.cg.shared.global [%0], [%1], 16;" :: "r"(dst), "l"(src) : "memory");
}
__device__ __forceinline__ void cp_commit() { asm volatile("cp.async.commit_group;" ::: "memory"); }
template<int N> __device__ __forceinline__ void cp_wait() {
    asm volatile("cp.async.wait_group %0;" :: "n"(N) : "memory");
}
__device__ __forceinline__ float sigmoidf_(float x) {
    return __fdividef(1.f, 1.f + __expf(-x));
}
__device__ __forceinline__ float tanhf_fast(float x) {
    float e = __expf(-2.f * x);
    return __fdividef(1.f - e, 1.f + e);
}

__device__ __forceinline__ void bsplit(float v, __nv_bfloat16& hi, __nv_bfloat16& lo) {
    hi = __float2bfloat16(v);
    lo = __float2bfloat16(v - __bfloat162float(hi));
}

// ---------------- kernel 0: pack Wh gate-major + build bf16 images ----------------
__global__ void pack_kernel(const float* __restrict__ X,
                            const float* __restrict__ Wxi, const float* __restrict__ Wxf,
                            const float* __restrict__ Wxo, const float* __restrict__ Wxz,
                            const float* __restrict__ Whi, const float* __restrict__ Whf,
                            const float* __restrict__ Who, const float* __restrict__ Whz,
                            const float* __restrict__ bi,  const float* __restrict__ bf,
                            const float* __restrict__ bo,  const float* __restrict__ bz) {
    int tid0 = blockIdx.x * blockDim.x + threadIdx.x;
    int stride = gridDim.x * blockDim.x;
    for (int idx = tid0; idx < HID_ * G4; idx += stride) {
        int k = idx >> 12, col = idx & 4095, g = col >> 10, j = col & 1023;
        const float* W = (g == 0) ? Whi : (g == 1) ? Whf : (g == 2) ? Who : Whz;
        g_Wh4[idx] = W[k * HID_ + j];
    }
    for (int idx = tid0; idx < G4; idx += stride) {
        int g = idx >> 10, j = idx & 1023;
        const float* b = (g == 0) ? bi : (g == 1) ? bf : (g == 2) ? bo : bz;
        g_b4[idx] = b[j];
    }
    for (int idx = tid0; idx < MROWS * (XD / 4); idx += stride) {
        int m = idx >> 7, kq = (idx & 127) * 4;
        float4 v = *(const float4*)&X[(size_t)m * XD + kq];
        __nv_bfloat16 h[4], l[4];
        bsplit(v.x, h[0], l[0]); bsplit(v.y, h[1], l[1]);
        bsplit(v.z, h[2], l[2]); bsplit(v.w, h[3], l[3]);
        int mt = m >> 7, mloc = m & 127, ck = kq >> 6, kloc = kq & 63;
        size_t off = (size_t)(mt * 8 + ck) * 16384 + (size_t)((mloc >> 3) << 10)
                   + (size_t)SW128(((mloc & 7) << 7) + (kloc << 1));
        *(uint2*)((char*)g_XH + off) = *(uint2*)h;
        *(uint2*)((char*)g_XL + off) = *(uint2*)l;
    }
    for (int idx = tid0; idx < G4 * (XD / 4); idx += stride) {
        int n = idx >> 7, kq = (idx & 127) * 4;
        int g = n >> 10, j = n & 1023;
        const float* W = (g == 0) ? Wxi : (g == 1) ? Wxf : (g == 2) ? Wxo : Wxz;
        __nv_bfloat16 h[4], l[4];
#pragma unroll
        for (int i = 0; i < 4; i++) bsplit(W[(size_t)(kq + i) * HID_ + j], h[i], l[i]);
        int nt = n >> 7, nloc = n & 127, ck = kq >> 6, kloc = kq & 63;
        size_t off = (size_t)(nt * 8 + ck) * 16384 + (size_t)((nloc >> 3) << 10)
                   + (size_t)SW128(((nloc & 7) << 7) + (kloc << 1));
        *(uint2*)((char*)g_WXH + off) = *(uint2*)h;
        *(uint2*)((char*)g_WXL + off) = *(uint2*)l;
    }
}

// ---------------- kernel A: xproj (HMMA bf16 3-product, cp.async pipeline) ----------------
#define XP_SMEM 131072

__global__ __launch_bounds__(512) void xproj_kernel() {
    extern __shared__ __align__(1024) char xs[];
    u32 smem_base = smem_u32(xs);
    int tid = threadIdx.x;
    int lane = tid & 31, wid = tid >> 5;
    int mw = wid & 3, nw = (wid >> 2) & 3;
    int ntb = blockIdx.x, mtb = blockIdx.y;

    int r128 = tid >> 7, lane128 = tid & 127;

    auto issue = [&](int ck, int stage) {
        size_t xb = (size_t)(mtb * 8 + ck) * 16384 + (size_t)lane128 * 16;
        size_t wb = (size_t)(ntb * 8 + ck) * 16384 + (size_t)lane128 * 16;
        const char* src = (r128 == 0) ? (const char*)g_XH + xb
                        : (r128 == 1) ? (const char*)g_XL + xb
                        : (r128 == 2) ? (const char*)g_WXH + wb
                                      : (const char*)g_WXL + wb;
        u32 dst = smem_base + stage * 65536 + r128 * 16384 + lane128 * 16;
#pragma unroll
        for (int q = 0; q < 8; q++) cp_async16(dst + q * 2048, src + q * 2048);
        cp_commit();
    };

    float acc[2][4][4];
#pragma unroll
    for (int i = 0; i < 2; i++)
#pragma unroll
        for (int j = 0; j < 4; j++)
#pragma unroll
            for (int q = 0; q < 4; q++) acc[i][j][q] = 0.f;

    issue(0, 0);

    int kbA = (lane & 16) ? 8 : 0;
    int kbB = lane & 8;
    int ar0 = mw * 32 + (lane & 15);
    int br0 = nw * 32 + (lane & 7) + ((lane & 16) ? 8 : 0);

    for (int ck = 0; ck < 8; ck++) {
        if (ck < 7) { issue(ck + 1, (ck + 1) & 1); cp_wait<1>(); }
        else cp_wait<0>();
        __syncthreads();
        u32 sb = smem_base + (ck & 1) * 65536;
#pragma unroll
        for (int ks = 0; ks < 4; ks++) {
            int klA = ks * 16 + kbA;
            int klB = ks * 16 + kbB;
            u32 ah[2][4], al[2][4], bh[2][4], bl[2][4];
#pragma unroll
            for (int mt2 = 0; mt2 < 2; mt2++) {
                int ar = ar0 + mt2 * 16;
                u32 aoff = (u32)((ar >> 3) << 10) + (u32)SW128(((ar & 7) << 7) + (klA << 1));
                ldsm4(ah[mt2][0], ah[mt2][1], ah[mt2][2], ah[mt2][3], sb + aoff);
                ldsm4(al[mt2][0], al[mt2][1], al[mt2][2], al[mt2][3], sb + 16384 + aoff);
            }
#pragma unroll
            for (int bg = 0; bg < 2; bg++) {
                int br = br0 + bg * 16;
                u32 boff = (u32)((br >> 3) << 10) + (u32)SW128(((br & 7) << 7) + (klB << 1));
                ldsm4(bh[bg][0], bh[bg][1], bh[bg][2], bh[bg][3], sb + 32768 + boff);
                ldsm4(bl[bg][0], bl[bg][1], bl[bg][2], bl[bg][3], sb + 49152 + boff);
            }
#pragma unroll
            for (int mt2 = 0; mt2 < 2; mt2++)
#pragma unroll
                for (int bg = 0; bg < 2; bg++) {
                    float* c0 = acc[mt2][bg * 2];
                    float* c1 = acc[mt2][bg * 2 + 1];
                    mma16816bf(c0, ah[mt2][0], ah[mt2][1], ah[mt2][2], ah[mt2][3], bh[bg][0], bh[bg][1]);
                    mma16816bf(c0, ah[mt2][0], ah[mt2][1], ah[mt2][2], ah[mt2][3], bl[bg][0], bl[bg][1]);
                    mma16816bf(c0, al[mt2][0], al[mt2][1], al[mt2][2], al[mt2][3], bh[bg][0], bh[bg][1]);
                    mma16816bf(c1, ah[mt2][0], ah[mt2][1], ah[mt2][2], ah[mt2][3], bh[bg][2], bh[bg][3]);
                    mma16816bf(c1, ah[mt2][0], ah[mt2][1], ah[mt2][2], ah[mt2][3], bl[bg][2], bl[bg][3]);
                    mma16816bf(c1, al[mt2][0], al[mt2][1], al[mt2][2], al[mt2][3], bh[bg][2], bh[bg][3]);
                }
        }
        __syncthreads();
    }

    int rowb = mtb * 128 + mw * 32;
    int colb = ntb * 128 + nw * 32;
    float2 bias[4];
#pragma unroll
    for (int nc = 0; nc < 4; nc++) {
        int col = colb + (nc >> 1) * 16 + (nc & 1) * 8 + (lane & 3) * 2;
        bias[nc] = *(const float2*)&g_b4[col];
    }
#pragma unroll
    for (int mt2 = 0; mt2 < 2; mt2++) {
        int r0 = rowb + mt2 * 16 + (lane >> 2);
#pragma unroll
        for (int nc = 0; nc < 4; nc++) {
            int col = colb + (nc >> 1) * 16 + (nc & 1) * 8 + (lane & 3) * 2;
            *(float2*)&g_xproj[(size_t)r0 * G4 + col] =
                make_float2(acc[mt2][nc][0] + bias[nc].x, acc[mt2][nc][1] + bias[nc].y);
            *(float2*)&g_xproj[(size_t)(r0 + 8) * G4 + col] =
                make_float2(acc[mt2][nc][2] + bias[nc].x, acc[mt2][nc][3] + bias[nc].y);
        }
    }
}

// ---------------- kernel B: persistent HMMA recurrence (fp16 single-product, deep prefetch) ----------------
// SMEM: [0,64K) Wh (fp16) | [64K, +34.8K) gsum
#define WHI_OFF   0
#define GSUM_OFF  65536
#define GROW      34
#define SMEM_BYTES (GSUM_OFF + 4 * BB * GROW * 4)

__device__ __forceinline__ void grid_sync(unsigned& phase) {
    __syncthreads();
    if (threadIdx.x == 0) {
        __threadfence();     // cumulative fence publishes the whole CTA's prior writes
        unsigned arrived = atomicAdd(&g_bar_cnt, 1u) + 1u;
        if (arrived == gridDim.x) {
            g_bar_cnt = 0;
            __threadfence();
            g_bar_phase = phase + 1u;
        } else {
            while (g_bar_phase == phase) { }
        }
        phase = phase + 1u;
        __threadfence();
    }
    __syncthreads();
}

__global__ __launch_bounds__(THR, 1) void lstm_kernel(float* __restrict__ out) {
    extern __shared__ __align__(1024) char sm[];
    u32 smem_base = smem_u32(sm);
    float* gsum = (float*)(sm + GSUM_OFF);
    int tid = threadIdx.x;
    int lane = tid & 31, wid = tid >> 5;
    int mt = wid & 1;                 // M-half
    int kq = wid >> 1;                // K-quarter
    int j0 = blockIdx.x * 8;

    // Wh slice -> single fp16 into SMEM atoms (8rows x 64cols, SW128)
    for (int idx = tid; idx < 32 * 1024; idx += THR) {
        int n = idx & 31, k = idx >> 5;
        int gc = (n >> 3) * 1024 + j0 + (n & 7);
        float wv = g_Wh4[(size_t)k * G4 + gc];
        __half hi = __float2half_rn(wv);
        u32 off = (u32)((n >> 3) + ((k >> 6) << 2)) * 1024u
                + (u32)SW128(((n & 7) << 7) + ((k & 63) << 1));
        *(__half*)(sm + WHI_OFF + off) = hi;
    }

    // ---- activation thread ownership + fragment write slot ----
    int ab = tid >> 2;                     // batch row 0..63
    int ajp = (tid & 3) * 2;               // j pair within CTA's 8 cols
    int rm = ab & 15;
    int w_mtile = ab >> 4;
    int w_ktile = blockIdx.x >> 1;         // (j0+ajp)>>4
    int w_L = (rm & 7) * 4 + (tid & 3);
    int w_r = ((rm >> 3) & 1) + ((blockIdx.x & 1) << 1);
    u32* wp = (u32*)&g_hfrag[0][w_ktile][w_mtile][w_L] + w_r;
    const size_t PAR_STRIDE_U32 = 64ull * 4 * 32 * 4;   // one parity in u32 units
    *wp = 0u;                              // zero parity-0 image
    float c0s = 0.f, c1s = 0.f;

    // mma B fragment address components
    int bcol_b = (lane & 7) + ((lane & 16) ? 8 : 0);
    int kbitB = lane & 8;

    unsigned phase = 0;
    if (tid == 0) phase = g_bar_phase;

    // xproj prefetch for step 0 (issued before the barrier: hides DRAM latency)
    const size_t xbase = ((size_t)ab * TT) * G4 + j0 + ajp;
    float2 xpv[4], xpn[4];
#pragma unroll
    for (int g = 0; g < 4; g++)
        xpv[g] = *(const float2*)&g_xproj[xbase + (size_t)g * 1024];

    grid_sync(phase);

    for (int t = 0; t < TT; t++) {
        int par = t & 1, npn = par ^ 1;
        const uint4* fH = &g_hfrag[par][0][0][0];

        float acc[2][4][4];
#pragma unroll
        for (int s = 0; s < 2; s++)
#pragma unroll
            for (int n = 0; n < 4; n++)
#pragma unroll
                for (int q = 0; q < 4; q++) acc[s][n][q] = 0.f;

        // rotating 3-slot A-fragment buffer, prefetch depth 2 (fully static indices)
        uint4 A[3][2][2];
#pragma unroll
        for (int pf = 0; pf < 2; pf++)
#pragma unroll
            for (int ks = 0; ks < 2; ks++)
#pragma unroll
                for (int sub = 0; sub < 2; sub++)
                    A[pf][ks][sub] = ldg_cg4(fH + ((pf * 8 + kq * 2 + ks) * 4 + (mt * 2 + sub)) * 32 + lane);

#pragma unroll
        for (int ck = 0; ck < 8; ck++) {
            if (ck + 2 < 8) {
#pragma unroll
                for (int ks = 0; ks < 2; ks++)
#pragma unroll
                    for (int sub = 0; sub < 2; sub++)
                        A[(ck + 2) % 3][ks][sub] =
                            ldg_cg4(fH + (((ck + 2) * 8 + kq * 2 + ks) * 4 + (mt * 2 + sub)) * 32 + lane);
            }
#pragma unroll
            for (int ks = 0; ks < 2; ks++) {
                int kB = ck * 128 + kq * 32 + ks * 16 + kbitB;
                u32 bh[2][4];
#pragma unroll
                for (int g16 = 0; g16 < 2; g16++) {
                    int bc = bcol_b + g16 * 16;
                    u32 boff = (u32)((bc >> 3) + ((kB >> 6) << 2)) * 1024u
                             + (u32)SW128(((bc & 7) << 7) + ((kB & 63) << 1));
                    ldsm4(bh[g16][0], bh[g16][1], bh[g16][2], bh[g16][3], smem_base + WHI_OFF + boff);
                }
#pragma unroll
                for (int sub = 0; sub < 2; sub++) {
                    uint4 ah = A[ck % 3][ks][sub];
#pragma unroll
                    for (int g16 = 0; g16 < 2; g16++) {
                        mma16816h(acc[sub][g16 * 2],     ah.x, ah.y, ah.z, ah.w, bh[g16][0], bh[g16][1]);
                        mma16816h(acc[sub][g16 * 2 + 1], ah.x, ah.y, ah.z, ah.w, bh[g16][2], bh[g16][3]);
                    }
                }
            }
        }

        // fragment writeback: per-warp K-quarter region
        {
            float* gq = gsum + (size_t)kq * BB * GROW;
#pragma unroll
            for (int sub = 0; sub < 2; sub++) {
                int r0 = mt * 32 + sub * 16 + (lane >> 2);
#pragma unroll
                for (int n8 = 0; n8 < 4; n8++) {
                    int cb = n8 * 8 + (lane & 3) * 2;
                    *(float2*)&gq[r0 * GROW + cb]       = make_float2(acc[sub][n8][0], acc[sub][n8][1]);
                    *(float2*)&gq[(r0 + 8) * GROW + cb] = make_float2(acc[sub][n8][2], acc[sub][n8][3]);
                }
            }
        }
        __syncthreads();

        // activation: 2 cells per thread, sum 4 K-quarters
        {
            float gg[4][2];
#pragma unroll
            for (int g = 0; g < 4; g++) { gg[g][0] = xpv[g].x; gg[g][1] = xpv[g].y; }
#pragma unroll
            for (int q = 0; q < 4; q++) {
                const float* gq = gsum + (size_t)q * BB * GROW + ab * GROW + ajp;
#pragma unroll
                for (int g = 0; g < 4; g++) {
                    float2 v = *(const float2*)&gq[g * 8];
                    gg[g][0] += v.x; gg[g][1] += v.y;
                }
            }
            float i0 = sigmoidf_(gg[0][0]), f0 = sigmoidf_(gg[1][0]), o0 = sigmoidf_(gg[2][0]), z0 = tanhf_fast(gg[3][0]);
            float i1 = sigmoidf_(gg[0][1]), f1 = sigmoidf_(gg[1][1]), o1 = sigmoidf_(gg[2][1]), z1 = tanhf_fast(gg[3][1]);
            c0s = i0 * z0 + f0 * c0s;
            c1s = i1 * z1 + f1 * c1s;
            float hv0 = o0 * tanhf_fast(c0s);
            float hv1 = o1 * tanhf_fast(c1s);
            // h-frag store FIRST (cross-CTA critical path), out store after
            __half h0 = __float2half_rn(hv0);
            __half h1 = __float2half_rn(hv1);
            u32 hw = (u32)__half_as_ushort(h0) | ((u32)__half_as_ushort(h1) << 16);
            wp[(size_t)npn * PAR_STRIDE_U32] = hw;
            *(float2*)&out[((size_t)ab * TT + t) * HID_ + j0 + ajp] = make_float2(hv0, hv1);
        }

        // prefetch next-step xproj BEFORE the barrier (resolves during the wait)
        if (t + 1 < TT) {
#pragma unroll
            for (int g = 0; g < 4; g++)
                xpn[g] = *(const float2*)&g_xproj[xbase + (size_t)(t + 1) * G4 + (size_t)g * 1024];
            grid_sync(phase);
#pragma unroll
            for (int g = 0; g < 4; g++) xpv[g] = xpn[g];
        }
    }
}

// ---------------- launch ----------------
extern "C" void kernel_launch(void* const* d_in, const int* in_sizes, int n_in,
                              void* d_out, int out_size) {
    const float* X   = (const float*)d_in[0];
    const float* Whi = (const float*)d_in[1];
    const float* Wxi = (const float*)d_in[2];
    const float* bi  = (const float*)d_in[3];
    const float* Whf = (const float*)d_in[4];
    const float* Wxf = (const float*)d_in[5];
    const float* bf  = (const float*)d_in[6];
    const float* Who = (const float*)d_in[7];
    const float* Wxo = (const float*)d_in[8];
    const float* bo  = (const float*)d_in[9];
    const float* Whz = (const float*)d_in[10];
    const float* Wxz = (const float*)d_in[11];
    const float* bz  = (const float*)d_in[12];

    pack_kernel<<<2048, 256>>>(X, Wxi, Wxf, Wxo, Wxz, Whi, Whf, Who, Whz, bi, bf, bo, bz);

    cudaFuncSetAttribute(xproj_kernel, cudaFuncAttributeMaxDynamicSharedMemorySize, XP_SMEM);
    dim3 gA(32, 256);
    xproj_kernel<<<gA, 512, XP_SMEM>>>();

    cudaFuncSetAttribute(lstm_kernel, cudaFuncAttributeMaxDynamicSharedMemorySize, SMEM_BYTES);
    lstm_kernel<<<NCTA, THR, SMEM_BYTES>>>((float*)d_out);
}

// round 15
// speedup vs baseline: 1.1548x; 1.0505x over previous
#include <cuda_runtime.h>
#include <cuda_bf16.h>
#include <cuda_fp16.h>
#include <cstdint>
#include <cstddef>

#define XD   512
#define HID_ 1024
#define BB   64
#define TT   512
#define G4   4096
#define MROWS 32768
#define NCTA 128
#define THR  256

typedef unsigned long long u64;
typedef unsigned int u32;

// ---------------- device scratch ----------------
__device__ __half g_Wh16[(size_t)HID_ * G4];                        // fp16 gate-major Wh
__device__ float g_b4[G4];
__device__ float g_xproj[(size_t)MROWS * G4];                       // X@Wx + bias
// h stored directly in mma A-fragment layout (single fp16 image): [parity][ktile(64)][mtile(4)][lane(32)]
__device__ __align__(16) uint4 g_hfrag[2][64][4][32];
__device__ __align__(16) __half g_XF[(size_t)MROWS * XD];           // X single fp16, swizzled atoms
__device__ __align__(16) __half g_WXH[(size_t)G4 * XD];             // Wx fp16 hi
__device__ __align__(16) __half g_WXL[(size_t)G4 * XD];             // Wx fp16 lo
__device__ unsigned g_bar_cnt;
__device__ volatile unsigned g_bar_phase;

// ---------------- helpers ----------------
#define SW128(x) ((x) ^ (((x) >> 3) & 0x70))

__device__ __forceinline__ u32 smem_u32(const void* p) {
    u32 a; asm("{ .reg .u64 t; cvta.to.shared.u64 t, %1; cvt.u32.u64 %0, t; }" : "=r"(a) : "l"(p));
    return a;
}
__device__ __forceinline__ void ldsm4(u32& r0, u32& r1, u32& r2, u32& r3, u32 addr) {
    asm volatile("ldmatrix.sync.aligned.m8n8.x4.shared.b16 {%0,%1,%2,%3}, [%4];"
                 : "=r"(r0), "=r"(r1), "=r"(r2), "=r"(r3) : "r"(addr));
}
__device__ __forceinline__ void mma16816h(float* c, u32 a0, u32 a1, u32 a2, u32 a3, u32 b0, u32 b1) {
    asm volatile("mma.sync.aligned.m16n8k16.row.col.f32.f16.f16.f32 "
                 "{%0,%1,%2,%3}, {%4,%5,%6,%7}, {%8,%9}, {%0,%1,%2,%3};"
                 : "+f"(c[0]), "+f"(c[1]), "+f"(c[2]), "+f"(c[3])
                 : "r"(a0), "r"(a1), "r"(a2), "r"(a3), "r"(b0), "r"(b1));
}
__device__ __forceinline__ uint4 ldg_cg4(const uint4* p) {
    uint4 v;
    asm volatile("ld.global.cg.v4.u32 {%0,%1,%2,%3}, [%4];"
                 : "=r"(v.x), "=r"(v.y), "=r"(v.z), "=r"(v.w) : "l"(p));
    return v;
}
__device__ __forceinline__ void cp_async16(u32 dst, const void* src) {
    asm volatile("cp.async.cg.shared.global [%0], [%1], 16;" :: "r"(dst), "l"(src) : "memory");
}
__device__ __forceinline__ void cp_commit() { asm volatile("cp.async.commit_group;" ::: "memory"); }
template<int N> __device__ __forceinline__ void cp_wait() {
    asm volatile("cp.async.wait_group %0;" :: "n"(N) : "memory");
}
__device__ __forceinline__ float sigmoidf_(float x) {
    return __fdividef(1.f, 1.f + __expf(-x));
}
__device__ __forceinline__ float tanhf_fast(float x) {
    float e = __expf(-2.f * x);
    return __fdividef(1.f - e, 1.f + e);
}

// ---------------- kernel 0: pack Wh (fp16) + fp16 images for xproj ----------------
__global__ void pack_kernel(const float* __restrict__ X,
                            const float* __restrict__ Wxi, const float* __restrict__ Wxf,
                            const float* __restrict__ Wxo, const float* __restrict__ Wxz,
                            const float* __restrict__ Whi, const float* __restrict__ Whf,
                            const float* __restrict__ Who, const float* __restrict__ Whz,
                            const float* __restrict__ bi,  const float* __restrict__ bf,
                            const float* __restrict__ bo,  const float* __restrict__ bz) {
    int tid0 = blockIdx.x * blockDim.x + threadIdx.x;
    int stride = gridDim.x * blockDim.x;
    for (int idx = tid0; idx < HID_ * G4; idx += stride) {
        int k = idx >> 12, col = idx & 4095, g = col >> 10, j = col & 1023;
        const float* W = (g == 0) ? Whi : (g == 1) ? Whf : (g == 2) ? Who : Whz;
        g_Wh16[idx] = __float2half_rn(W[k * HID_ + j]);
    }
    for (int idx = tid0; idx < G4; idx += stride) {
        int g = idx >> 10, j = idx & 1023;
        const float* b = (g == 0) ? bi : (g == 1) ? bf : (g == 2) ? bo : bz;
        g_b4[idx] = b[j];
    }
    // X image: single fp16, blocked atoms per (mt, ck)
    for (int idx = tid0; idx < MROWS * (XD / 4); idx += stride) {
        int m = idx >> 7, kq = (idx & 127) * 4;
        float4 v = *(const float4*)&X[(size_t)m * XD + kq];
        __half h[4];
        h[0] = __float2half_rn(v.x); h[1] = __float2half_rn(v.y);
        h[2] = __float2half_rn(v.z); h[3] = __float2half_rn(v.w);
        int mt = m >> 7, mloc = m & 127, ck = kq >> 6, kloc = kq & 63;
        size_t off = (size_t)(mt * 8 + ck) * 16384 + (size_t)((mloc >> 3) << 10)
                   + (size_t)SW128(((mloc & 7) << 7) + (kloc << 1));
        *(uint2*)((char*)g_XF + off) = *(uint2*)h;
    }
    // Wx image: fp16 hi/lo (exact split to 2^-22)
    for (int idx = tid0; idx < G4 * (XD / 4); idx += stride) {
        int n = idx >> 7, kq = (idx & 127) * 4;
        int g = n >> 10, j = n & 1023;
        const float* W = (g == 0) ? Wxi : (g == 1) ? Wxf : (g == 2) ? Wxo : Wxz;
        __half h[4], l[4];
#pragma unroll
        for (int i = 0; i < 4; i++) {
            float wv = W[(size_t)(kq + i) * HID_ + j];
            h[i] = __float2half_rn(wv);
            l[i] = __float2half_rn(wv - __half2float(h[i]));
        }
        int nt = n >> 7, nloc = n & 127, ck = kq >> 6, kloc = kq & 63;
        size_t off = (size_t)(nt * 8 + ck) * 16384 + (size_t)((nloc >> 3) << 10)
                   + (size_t)SW128(((nloc & 7) << 7) + (kloc << 1));
        *(uint2*)((char*)g_WXH + off) = *(uint2*)h;
        *(uint2*)((char*)g_WXL + off) = *(uint2*)l;
    }
}

// ---------------- kernel A: xproj (HMMA fp16 2-product, cp.async pipeline) ----------------
// stage = [XF 16K][WXH 16K][WXL 16K] = 48KB, double buffered
#define XP_STAGE 49152
#define XP_SMEM  (2 * XP_STAGE)

__global__ __launch_bounds__(512) void xproj_kernel() {
    extern __shared__ __align__(1024) char xs[];
    u32 smem_base = smem_u32(xs);
    int tid = threadIdx.x;
    int lane = tid & 31, wid = tid >> 5;
    int mw = wid & 3, nw = (wid >> 2) & 3;
    int ntb = blockIdx.x, mtb = blockIdx.y;

    auto issue = [&](int ck, int stage) {
        size_t xb = (size_t)(mtb * 8 + ck) * 16384;
        size_t wb = (size_t)(ntb * 8 + ck) * 16384;
        u32 dst = smem_base + stage * XP_STAGE;
        u32 o = (u32)tid * 32;
        cp_async16(dst + o,                 (const char*)g_XF  + xb + o);
        cp_async16(dst + o + 16,            (const char*)g_XF  + xb + o + 16);
        cp_async16(dst + 16384 + o,         (const char*)g_WXH + wb + o);
        cp_async16(dst + 16384 + o + 16,    (const char*)g_WXH + wb + o + 16);
        cp_async16(dst + 32768 + o,         (const char*)g_WXL + wb + o);
        cp_async16(dst + 32768 + o + 16,    (const char*)g_WXL + wb + o + 16);
        cp_commit();
    };

    float acc[2][4][4];
#pragma unroll
    for (int i = 0; i < 2; i++)
#pragma unroll
        for (int j = 0; j < 4; j++)
#pragma unroll
            for (int q = 0; q < 4; q++) acc[i][j][q] = 0.f;

    issue(0, 0);

    int kbA = (lane & 16) ? 8 : 0;
    int kbB = lane & 8;
    int ar0 = mw * 32 + (lane & 15);
    int br0 = nw * 32 + (lane & 7) + ((lane & 16) ? 8 : 0);

    for (int ck = 0; ck < 8; ck++) {
        if (ck < 7) { issue(ck + 1, (ck + 1) & 1); cp_wait<1>(); }
        else cp_wait<0>();
        __syncthreads();
        u32 sb = smem_base + (ck & 1) * XP_STAGE;
#pragma unroll
        for (int ks = 0; ks < 4; ks++) {
            int klA = ks * 16 + kbA;
            int klB = ks * 16 + kbB;
            u32 ah[2][4], bh[2][4], bl[2][4];
#pragma unroll
            for (int mt2 = 0; mt2 < 2; mt2++) {
                int ar = ar0 + mt2 * 16;
                u32 aoff = (u32)((ar >> 3) << 10) + (u32)SW128(((ar & 7) << 7) + (klA << 1));
                ldsm4(ah[mt2][0], ah[mt2][1], ah[mt2][2], ah[mt2][3], sb + aoff);
            }
#pragma unroll
            for (int bg = 0; bg < 2; bg++) {
                int br = br0 + bg * 16;
                u32 boff = (u32)((br >> 3) << 10) + (u32)SW128(((br & 7) << 7) + (klB << 1));
                ldsm4(bh[bg][0], bh[bg][1], bh[bg][2], bh[bg][3], sb + 16384 + boff);
                ldsm4(bl[bg][0], bl[bg][1], bl[bg][2], bl[bg][3], sb + 32768 + boff);
            }
#pragma unroll
            for (int mt2 = 0; mt2 < 2; mt2++)
#pragma unroll
                for (int bg = 0; bg < 2; bg++) {
                    float* c0 = acc[mt2][bg * 2];
                    float* c1 = acc[mt2][bg * 2 + 1];
                    mma16816h(c0, ah[mt2][0], ah[mt2][1], ah[mt2][2], ah[mt2][3], bh[bg][0], bh[bg][1]);
                    mma16816h(c0, ah[mt2][0], ah[mt2][1], ah[mt2][2], ah[mt2][3], bl[bg][0], bl[bg][1]);
                    mma16816h(c1, ah[mt2][0], ah[mt2][1], ah[mt2][2], ah[mt2][3], bh[bg][2], bh[bg][3]);
                    mma16816h(c1, ah[mt2][0], ah[mt2][1], ah[mt2][2], ah[mt2][3], bl[bg][2], bl[bg][3]);
                }
        }
        __syncthreads();
    }

    int rowb = mtb * 128 + mw * 32;
    int colb = ntb * 128 + nw * 32;
    float2 bias[4];
#pragma unroll
    for (int nc = 0; nc < 4; nc++) {
        int col = colb + (nc >> 1) * 16 + (nc & 1) * 8 + (lane & 3) * 2;
        bias[nc] = *(const float2*)&g_b4[col];
    }
#pragma unroll
    for (int mt2 = 0; mt2 < 2; mt2++) {
        int r0 = rowb + mt2 * 16 + (lane >> 2);
#pragma unroll
        for (int nc = 0; nc < 4; nc++) {
            int col = colb + (nc >> 1) * 16 + (nc & 1) * 8 + (lane & 3) * 2;
            *(float2*)&g_xproj[(size_t)r0 * G4 + col] =
                make_float2(acc[mt2][nc][0] + bias[nc].x, acc[mt2][nc][1] + bias[nc].y);
            *(float2*)&g_xproj[(size_t)(r0 + 8) * G4 + col] =
                make_float2(acc[mt2][nc][2] + bias[nc].x, acc[mt2][nc][3] + bias[nc].y);
        }
    }
}

// ---------------- kernel B: persistent HMMA recurrence (fp16 single-product, deep prefetch) ----------------
// SMEM: [0,64K) Wh (fp16) | [64K, +34.8K) gsum
#define WHI_OFF   0
#define GSUM_OFF  65536
#define GROW      34
#define SMEM_BYTES (GSUM_OFF + 4 * BB * GROW * 4)

__device__ __forceinline__ void grid_sync(unsigned& phase) {
    __syncthreads();
    if (threadIdx.x == 0) {
        __threadfence();
        unsigned arrived = atomicAdd(&g_bar_cnt, 1u) + 1u;
        if (arrived == gridDim.x) {
            g_bar_cnt = 0;
            __threadfence();
            g_bar_phase = phase + 1u;
        } else {
            while (g_bar_phase == phase) { }
        }
        phase = phase + 1u;
        __threadfence();
    }
    __syncthreads();
}

__global__ __launch_bounds__(THR, 1) void lstm_kernel(float* __restrict__ out) {
    extern __shared__ __align__(1024) char sm[];
    u32 smem_base = smem_u32(sm);
    float* gsum = (float*)(sm + GSUM_OFF);
    int tid = threadIdx.x;
    int lane = tid & 31, wid = tid >> 5;
    int mt = wid & 1;                 // M-half
    int kq = wid >> 1;                // K-quarter
    int j0 = blockIdx.x * 8;

    // Wh slice (already fp16) into SMEM atoms (8rows x 64cols, SW128)
    for (int idx = tid; idx < 32 * 1024; idx += THR) {
        int n = idx & 31, k = idx >> 5;
        int gc = (n >> 3) * 1024 + j0 + (n & 7);
        __half hv = g_Wh16[(size_t)k * G4 + gc];
        u32 off = (u32)((n >> 3) + ((k >> 6) << 2)) * 1024u
                + (u32)SW128(((n & 7) << 7) + ((k & 63) << 1));
        *(__half*)(sm + WHI_OFF + off) = hv;
    }

    // ---- activation thread ownership + fragment write slot ----
    int ab = tid >> 2;                     // batch row 0..63
    int ajp = (tid & 3) * 2;               // j pair within CTA's 8 cols
    int rm = ab & 15;
    int w_mtile = ab >> 4;
    int w_ktile = blockIdx.x >> 1;
    int w_L = (rm & 7) * 4 + (tid & 3);
    int w_r = ((rm >> 3) & 1) + ((blockIdx.x & 1) << 1);
    u32* wp = (u32*)&g_hfrag[0][w_ktile][w_mtile][w_L] + w_r;
    const size_t PAR_STRIDE_U32 = 64ull * 4 * 32 * 4;
    *wp = 0u;                              // zero parity-0 image
    float c0s = 0.f, c1s = 0.f;

    // mma B fragment address components
    int bcol_b = (lane & 7) + ((lane & 16) ? 8 : 0);
    int kbitB = lane & 8;

    unsigned phase = 0;
    if (tid == 0) phase = g_bar_phase;

    // xproj prefetch for step 0
    const size_t xbase = ((size_t)ab * TT) * G4 + j0 + ajp;
    float2 xpv[4], xpn[4];
#pragma unroll
    for (int g = 0; g < 4; g++)
        xpv[g] = *(const float2*)&g_xproj[xbase + (size_t)g * 1024];

    grid_sync(phase);

    for (int t = 0; t < TT; t++) {
        int par = t & 1, npn = par ^ 1;
        const uint4* fH = &g_hfrag[par][0][0][0];

        float acc[2][4][4];
#pragma unroll
        for (int s = 0; s < 2; s++)
#pragma unroll
            for (int n = 0; n < 4; n++)
#pragma unroll
                for (int q = 0; q < 4; q++) acc[s][n][q] = 0.f;

        // rotating 3-slot A-fragment buffer, prefetch depth 2
        uint4 A[3][2][2];
#pragma unroll
        for (int pf = 0; pf < 2; pf++)
#pragma unroll
            for (int ks = 0; ks < 2; ks++)
#pragma unroll
                for (int sub = 0; sub < 2; sub++)
                    A[pf][ks][sub] = ldg_cg4(fH + ((pf * 8 + kq * 2 + ks) * 4 + (mt * 2 + sub)) * 32 + lane);

#pragma unroll
        for (int ck = 0; ck < 8; ck++) {
            if (ck + 2 < 8) {
#pragma unroll
                for (int ks = 0; ks < 2; ks++)
#pragma unroll
                    for (int sub = 0; sub < 2; sub++)
                        A[(ck + 2) % 3][ks][sub] =
                            ldg_cg4(fH + (((ck + 2) * 8 + kq * 2 + ks) * 4 + (mt * 2 + sub)) * 32 + lane);
            }
#pragma unroll
            for (int ks = 0; ks < 2; ks++) {
                int kB = ck * 128 + kq * 32 + ks * 16 + kbitB;
                u32 bh[2][4];
#pragma unroll
                for (int g16 = 0; g16 < 2; g16++) {
                    int bc = bcol_b + g16 * 16;
                    u32 boff = (u32)((bc >> 3) + ((kB >> 6) << 2)) * 1024u
                             + (u32)SW128(((bc & 7) << 7) + ((kB & 63) << 1));
                    ldsm4(bh[g16][0], bh[g16][1], bh[g16][2], bh[g16][3], smem_base + WHI_OFF + boff);
                }
#pragma unroll
                for (int sub = 0; sub < 2; sub++) {
                    uint4 ah = A[ck % 3][ks][sub];
#pragma unroll
                    for (int g16 = 0; g16 < 2; g16++) {
                        mma16816h(acc[sub][g16 * 2],     ah.x, ah.y, ah.z, ah.w, bh[g16][0], bh[g16][1]);
                        mma16816h(acc[sub][g16 * 2 + 1], ah.x, ah.y, ah.z, ah.w, bh[g16][2], bh[g16][3]);
                    }
                }
            }
        }

        // fragment writeback: per-warp K-quarter region
        {
            float* gq = gsum + (size_t)kq * BB * GROW;
#pragma unroll
            for (int sub = 0; sub < 2; sub++) {
                int r0 = mt * 32 + sub * 16 + (lane >> 2);
#pragma unroll
                for (int n8 = 0; n8 < 4; n8++) {
                    int cb = n8 * 8 + (lane & 3) * 2;
                    *(float2*)&gq[r0 * GROW + cb]       = make_float2(acc[sub][n8][0], acc[sub][n8][1]);
                    *(float2*)&gq[(r0 + 8) * GROW + cb] = make_float2(acc[sub][n8][2], acc[sub][n8][3]);
                }
            }
        }
        __syncthreads();

        // activation: 2 cells per thread, sum 4 K-quarters
        {
            float gg[4][2];
#pragma unroll
            for (int g = 0; g < 4; g++) { gg[g][0] = xpv[g].x; gg[g][1] = xpv[g].y; }
#pragma unroll
            for (int q = 0; q < 4; q++) {
                const float* gq = gsum + (size_t)q * BB * GROW + ab * GROW + ajp;
#pragma unroll
                for (int g = 0; g < 4; g++) {
                    float2 v = *(const float2*)&gq[g * 8];
                    gg[g][0] += v.x; gg[g][1] += v.y;
                }
            }
            float i0 = sigmoidf_(gg[0][0]), f0 = sigmoidf_(gg[1][0]), o0 = sigmoidf_(gg[2][0]), z0 = tanhf_fast(gg[3][0]);
            float i1 = sigmoidf_(gg[0][1]), f1 = sigmoidf_(gg[1][1]), o1 = sigmoidf_(gg[2][1]), z1 = tanhf_fast(gg[3][1]);
            c0s = i0 * z0 + f0 * c0s;
            c1s = i1 * z1 + f1 * c1s;
            float hv0 = o0 * tanhf_fast(c0s);
            float hv1 = o1 * tanhf_fast(c1s);
            // h-frag store FIRST (cross-CTA critical path), out store after
            __half h0 = __float2half_rn(hv0);
            __half h1 = __float2half_rn(hv1);
            u32 hw = (u32)__half_as_ushort(h0) | ((u32)__half_as_ushort(h1) << 16);
            wp[(size_t)npn * PAR_STRIDE_U32] = hw;
            *(float2*)&out[((size_t)ab * TT + t) * HID_ + j0 + ajp] = make_float2(hv0, hv1);
        }

        // prefetch next-step xproj BEFORE the barrier (resolves during the wait)
        if (t + 1 < TT) {
#pragma unroll
            for (int g = 0; g < 4; g++)
                xpn[g] = *(const float2*)&g_xproj[xbase + (size_t)(t + 1) * G4 + (size_t)g * 1024];
            grid_sync(phase);
#pragma unroll
            for (int g = 0; g < 4; g++) xpv[g] = xpn[g];
        }
    }
}

// ---------------- launch ----------------
extern "C" void kernel_launch(void* const* d_in, const int* in_sizes, int n_in,
                              void* d_out, int out_size) {
    const float* X   = (const float*)d_in[0];
    const float* Whi = (const float*)d_in[1];
    const float* Wxi = (const float*)d_in[2];
    const float* bi  = (const float*)d_in[3];
    const float* Whf = (const float*)d_in[4];
    const float* Wxf = (const float*)d_in[5];
    const float* bf  = (const float*)d_in[6];
    const float* Who = (const float*)d_in[7];
    const float* Wxo = (const float*)d_in[8];
    const float* bo  = (const float*)d_in[9];
    const float* Whz = (const float*)d_in[10];
    const float* Wxz = (const float*)d_in[11];
    const float* bz  = (const float*)d_in[12];

    pack_kernel<<<2048, 256>>>(X, Wxi, Wxf, Wxo, Wxz, Whi, Whf, Who, Whz, bi, bf, bo, bz);

    cudaFuncSetAttribute(xproj_kernel, cudaFuncAttributeMaxDynamicSharedMemorySize, XP_SMEM);
    dim3 gA(32, 256);
    xproj_kernel<<<gA, 512, XP_SMEM>>>();

    cudaFuncSetAttribute(lstm_kernel, cudaFuncAttributeMaxDynamicSharedMemorySize, SMEM_BYTES);
    lstm_kernel<<<NCTA, THR, SMEM_BYTES>>>((float*)d_out);
}